// round 14
// baseline (speedup 1.0000x reference)
#include <cuda_runtime.h>
#include <cstdint>

#define RES   512
#define NPTS  1024            // 8 curves * 128 steps
// exponent in cell units: (xk - i/512)^2*5000 == (xi - i)^2 * (5000/2^18)
#define INVC_CELL 0.019073486328125f   // 5000 / 262144, exact in fp32
// Dropped terms <= exp(-5000*(30/512)^2) = 3.5e-8 each (validated at R13).
#define BAND  30.0f

#define NT  32                // tiles per dimension
#define TI  16                // tile i
#define TJ  16                // tile j
#define MAXE NPTS             // per-tile entry cap (hard upper bound)

#define FMA_F32X2(d, a, b) \
    asm("fma.rn.f32x2 %0, %1, %2, %0;" : "+l"(d) : "l"(a), "l"(b))
#define ADD_F32X2(d, a, b) \
    asm("add.rn.f32x2 %0, %1, %2;" : "=l"(d) : "l"(a), "l"(b))

// Per-tile point lists (cell coords), built once by k_prep. 8 MB static.
__device__ float2 g_tlist[NT][NT][MAXE];
__device__ int    g_tn[NT][NT];

// ---------------------------------------------------------------------------
// Kernel A: Bezier evaluation + 2D per-tile binning.
// One block per i-strip (32 blocks, 128 threads).
//  stage 1: x-filter into smem (order-preserving, ascending k)
//  stage 2: warp w ballot-compacts j-tiles w, w+4, ... into g_tlist
// ---------------------------------------------------------------------------
__global__ __launch_bounds__(128) void k_prep(const float* __restrict__ curves) {
    __shared__ float2 spt[NPTS];             // 8 KB
    __shared__ int wsum[4], woff[4], s_n;
    const int tid = threadIdx.x, lane = tid & 31, w = tid >> 5;
    const int strip = blockIdx.x;
    const float ilo = (float)(strip * TI) - BAND;
    const float ihi = (float)(strip * TI + TI - 1) + BAND;

    // ---- stage 1: Bezier + x-filter compaction ----------------------------
    float xi[8], yi[8];
    bool ok[8];
    int cnt = 0;
    const int kb = tid * 8;                  // 8 consecutive k, same curve
    const int c  = kb >> 7;
    const float* P = curves + c * 8;
    float p0x = __ldg(P+0), p0y = __ldg(P+1), p1x = __ldg(P+2), p1y = __ldg(P+3);
    float p2x = __ldg(P+4), p2y = __ldg(P+5), p3x = __ldg(P+6), p3y = __ldg(P+7);
    #pragma unroll
    for (int u = 0; u < 8; u++) {
        float t = (float)((kb + u) & 127) * (1.0f / 127.0f);
        float a01 = p0x + (p1x - p0x) * t;
        float a12 = p1x + (p2x - p1x) * t;
        float a23 = p2x + (p3x - p2x) * t;
        float qa  = a01 + t * (a12 - a01);
        float qb  = a12 + t * (a23 - a12);
        xi[u] = (qa + t * (qb - qa)) * (float)RES;
        a01 = p0y + (p1y - p0y) * t;
        a12 = p1y + (p2y - p1y) * t;
        a23 = p2y + (p3y - p2y) * t;
        qa  = a01 + t * (a12 - a01);
        qb  = a12 + t * (a23 - a12);
        yi[u] = (qa + t * (qb - qa)) * (float)RES;
        ok[u] = (xi[u] >= ilo) & (xi[u] <= ihi);
        cnt += ok[u] ? 1 : 0;
    }
    int inc = cnt;                           // warp inclusive scan
    #pragma unroll
    for (int d = 1; d < 32; d <<= 1) {
        int v = __shfl_up_sync(0xffffffffu, inc, d);
        if (lane >= d) inc += v;
    }
    if (lane == 31) wsum[w] = inc;
    __syncthreads();
    if (tid == 0) {
        int s = 0;
        #pragma unroll
        for (int q = 0; q < 4; q++) { woff[q] = s; s += wsum[q]; }
        s_n = s;
    }
    __syncthreads();
    int off = woff[w] + inc - cnt;
    #pragma unroll
    for (int u = 0; u < 8; u++)
        if (ok[u]) spt[off++] = make_float2(xi[u], yi[u]);
    __syncthreads();
    const int n = s_n;

    // ---- stage 2: per-j-tile ballot compaction into global ----------------
    for (int it = 0; it < 8; it++) {
        int jt = it * 4 + w;                 // this warp's j-tile
        float jlo = (float)(jt * TJ) - BAND;
        float jhi = (float)(jt * TJ + TJ - 1) + BAND;
        int tout = 0;
        for (int base = 0; base < n; base += 32) {
            int k = base + lane;
            bool acc = false;
            float2 p;
            if (k < n) {
                p = spt[k];
                acc = (p.y >= jlo) & (p.y <= jhi);
            }
            unsigned m = __ballot_sync(0xffffffffu, acc);
            if (acc)
                g_tlist[strip][jt][tout + __popc(m & ((1u << lane) - 1u))] = p;
            tout += __popc(m);
        }
        if (lane == 0) g_tn[strip][jt] = tout;
    }
}

// ---------------------------------------------------------------------------
// Kernel B: one 16x16 tile per block (grid 32x32), 128 threads = 4 warps,
// warp-level split-K over 8-point chunks. No block barriers in the main loop.
//  lane roles per chunk: (pl = lane>>2, sub = lane&3) computes 4 ex + 4 ey
//  (ey stored duplicated) for point pl; then (tx = lane&3, ty2 = lane>>2)
//  accumulates a 4(i) x 2(j) microtile with FFMA2.
// ---------------------------------------------------------------------------
__global__ __launch_bounds__(128) void k_tile(float* __restrict__ out) {
    __shared__ float2 slist[MAXE];                // 8 KB
    __shared__ float  sex [4][8][16];             // 2 KB
    __shared__ float  seyd[4][8][32];             // 4 KB (ey duplicated)
    __shared__ unsigned long long sacc[4][32][4]; // 4 KB

    const int tid = threadIdx.x, lane = tid & 31, w = tid >> 5;
    const int ti = blockIdx.x, tj = blockIdx.y;
    const int i0 = ti * TI, j0 = tj * TJ;

    const int nk = g_tn[ti][tj];
    if (nk == 0) {
        if (tid < 64)
            *(float4*)&out[(j0 + (tid >> 2)) * RES + i0 + (tid & 3) * 4] =
                make_float4(0.f, 0.f, 0.f, 0.f);
        return;
    }

    // ---- load this tile's list (2 points per float4) ----------------------
    for (int idx = tid; idx * 2 < nk; idx += 128)
        *(float4*)&slist[idx * 2] = *(const float4*)&g_tlist[ti][tj][idx * 2];
    __syncthreads();

    // ---- warp-autonomous split-K main loop --------------------------------
    const int pl  = lane >> 2;      // point slot 0..7 (staging)
    const int sub = lane & 3;       // 4-cell group   (staging)
    const int tx  = lane & 3;       // i microtile    (compute)
    const int ty2 = lane >> 2;      // j pair 0..7    (compute)
    unsigned long long a00 = 0ull, a01 = 0ull, a10 = 0ull, a11 = 0ull;

    for (int cb = w * 8; cb < nk; cb += 32) {
        float4 exv = make_float4(0.f, 0.f, 0.f, 0.f);
        float4 ey01 = make_float4(0.f, 0.f, 0.f, 0.f);
        float4 ey23 = make_float4(0.f, 0.f, 0.f, 0.f);
        int idx = cb + pl;
        if (idx < nk) {
            float2 p = slist[idx];
            float bi = (float)(i0 + sub * 4);
            float bj = (float)(j0 + sub * 4);
            float d, e0, e1, e2, e3;
            d = p.x - (bi + 0.f); exv.x = __expf(-d * d * INVC_CELL);
            d = p.x - (bi + 1.f); exv.y = __expf(-d * d * INVC_CELL);
            d = p.x - (bi + 2.f); exv.z = __expf(-d * d * INVC_CELL);
            d = p.x - (bi + 3.f); exv.w = __expf(-d * d * INVC_CELL);
            d = p.y - (bj + 0.f); e0 = __expf(-d * d * INVC_CELL);
            d = p.y - (bj + 1.f); e1 = __expf(-d * d * INVC_CELL);
            d = p.y - (bj + 2.f); e2 = __expf(-d * d * INVC_CELL);
            d = p.y - (bj + 3.f); e3 = __expf(-d * d * INVC_CELL);
            ey01 = make_float4(e0, e0, e1, e1);
            ey23 = make_float4(e2, e2, e3, e3);
        }
        __syncwarp();                        // readers of prev chunk done
        *(float4*)&sex [w][pl][sub * 4]     = exv;
        *(float4*)&seyd[w][pl][sub * 8]     = ey01;
        *(float4*)&seyd[w][pl][sub * 8 + 4] = ey23;
        __syncwarp();

        #pragma unroll
        for (int p = 0; p < 8; p++) {
            unsigned long long e0 =
                *(const unsigned long long*)&seyd[w][p][(ty2 * 2) * 2];
            unsigned long long e1 =
                *(const unsigned long long*)&seyd[w][p][(ty2 * 2 + 1) * 2];
            ulonglong2 ex2 = *(const ulonglong2*)&sex[w][p][tx * 4];
            FMA_F32X2(a00, ex2.x, e0);
            FMA_F32X2(a01, ex2.y, e0);
            FMA_F32X2(a10, ex2.x, e1);
            FMA_F32X2(a11, ex2.y, e1);
        }
    }

    // ---- fixed-order 4-warp combine + write -------------------------------
    sacc[w][lane][0] = a00;  sacc[w][lane][1] = a01;
    sacc[w][lane][2] = a10;  sacc[w][lane][3] = a11;
    __syncthreads();
    {
        const int l = tid & 31, s = tid >> 5;   // lane l, slot s
        unsigned long long v = sacc[0][l][s], t;
        ADD_F32X2(t, v, sacc[1][l][s]); v = t;
        ADD_F32X2(t, v, sacc[2][l][s]); v = t;
        ADD_F32X2(t, v, sacc[3][l][s]); v = t;
        int ltx = l & 3, lty2 = l >> 2;
        int jj = s >> 1, ip = s & 1;
        int i = i0 + ltx * 4 + ip * 2;
        int j = j0 + lty2 * 2 + jj;
        *(unsigned long long*)&out[j * RES + i] = v;
    }
}

// ---------------------------------------------------------------------------
extern "C" void kernel_launch(void* const* d_in, const int* in_sizes, int n_in,
                              void* d_out, int out_size) {
    const float* curves = (const float*)d_in[0];
    float* out = (float*)d_out;
    k_prep<<<NT, 128>>>(curves);
    dim3 grid(NT, NT);
    k_tile<<<grid, 128>>>(out);
}

// round 15
// speedup vs baseline: 1.5373x; 1.5373x over previous
#include <cuda_runtime.h>
#include <cstdint>

#define RES   512
#define NPTS  1024            // 8 curves * 128 steps
// exponent in cell units: (xk - i/512)^2*5000 == (xi - i)^2 * (5000/2^18)
#define INVC_CELL 0.019073486328125f   // 5000 / 262144, exact in fp32
// Dropped terms <= exp(-5000*(30/512)^2) = 3.5e-8 each (validated R13/R14).
#define BAND  30.0f

#define NT  32                // tiles per dimension
#define TI  16                // tile i
#define TJ  16                // tile j

#define FMA_F32X2(d, a, b) \
    asm("fma.rn.f32x2 %0, %1, %2, %0;" : "+l"(d) : "l"(a), "l"(b))
#define ADD_F32X2(d, a, b) \
    asm("add.rn.f32x2 %0, %1, %2;" : "=l"(d) : "l"(a), "l"(b))

// ---------------------------------------------------------------------------
// Single fused kernel: one block per 16x16 tile (grid 32x32), 128 threads.
//  1. Bezier: thread tid evaluates all 8 curves at t = tid/127
//     (control points are block-uniform loads; k = curve*128 + tid).
//  2. Warp-private ballot compaction of in-band points (no block barriers).
//     Warp w holds k with (k mod 128) in [w*32, w*32+32) -> consecutive
//     curve runs are split ~evenly across warps (intra-block split-K).
//  3. Warp-autonomous main loop (chunks of 8 points): lanes compute
//     4 ex + 4 ey __expf each (ey duplicated for f32x2), 2 syncwarps,
//     then 8 x (2 LDS.64 + 1 LDS.128 + 4 FFMA2) microtile accumulate.
//  4. Fixed-order 4-warp combine, coalesced write.
// ---------------------------------------------------------------------------
__global__ __launch_bounds__(128) void k_fused(const float* __restrict__ curves,
                                               float* __restrict__ out) {
    __shared__ float2 wlist[4][256];              // 8 KB warp-private lists
    __shared__ float  sex [4][8][16];             // 2 KB
    __shared__ float  seyd[4][8][32];             // 4 KB (ey duplicated)
    __shared__ unsigned long long sacc[4][32][4]; // 4 KB

    const int tid = threadIdx.x, lane = tid & 31, w = tid >> 5;
    const int i0 = blockIdx.x * TI, j0 = blockIdx.y * TJ;

    // ---- 1+2. Bezier eval (8 curves at one t) + warp-private compaction ---
    const float t = (float)tid * (1.0f / 127.0f);
    const float ilo = (float)i0 - BAND, ihi = (float)(i0 + TI - 1) + BAND;
    const float jlo = (float)j0 - BAND, jhi = (float)(j0 + TJ - 1) + BAND;
    const unsigned lmlt = (1u << lane) - 1u;
    int nkw = 0;
    #pragma unroll
    for (int u = 0; u < 8; u++) {
        const float4* P4 = (const float4*)(curves + u * 8);
        float4 A = __ldg(P4);        // p0x p0y p1x p1y (uniform across block)
        float4 B = __ldg(P4 + 1);    // p2x p2y p3x p3y
        float a01 = A.x + (A.z - A.x) * t;
        float a12 = A.z + (B.x - A.z) * t;
        float a23 = B.x + (B.z - B.x) * t;
        float qa  = a01 + t * (a12 - a01);
        float qb  = a12 + t * (a23 - a12);
        float xi  = (qa + t * (qb - qa)) * (float)RES;
        a01 = A.y + (A.w - A.y) * t;
        a12 = A.w + (B.y - A.w) * t;
        a23 = B.y + (B.w - B.y) * t;
        qa  = a01 + t * (a12 - a01);
        qb  = a12 + t * (a23 - a12);
        float yi  = (qa + t * (qb - qa)) * (float)RES;

        bool ok = (xi >= ilo) & (xi <= ihi) & (yi >= jlo) & (yi <= jhi);
        unsigned m = __ballot_sync(0xffffffffu, ok);
        if (ok) wlist[w][nkw + __popc(m & lmlt)] = make_float2(xi, yi);
        nkw += __popc(m);
    }
    __syncwarp();

    // ---- 3. warp-autonomous main loop over this warp's list ---------------
    const int pl  = lane >> 2;      // point slot 0..7 (staging)
    const int sub = lane & 3;       // 4-cell group   (staging)
    const int tx  = lane & 3;       // i microtile    (compute)
    const int ty2 = lane >> 2;      // j pair 0..7    (compute)
    unsigned long long a00 = 0ull, a01v = 0ull, a10 = 0ull, a11 = 0ull;

    for (int cb = 0; cb < nkw; cb += 8) {
        float4 exv  = make_float4(0.f, 0.f, 0.f, 0.f);
        float4 ey01 = make_float4(0.f, 0.f, 0.f, 0.f);
        float4 ey23 = make_float4(0.f, 0.f, 0.f, 0.f);
        int idx = cb + pl;
        if (idx < nkw) {
            float2 p = wlist[w][idx];
            float bi = (float)(i0 + sub * 4);
            float bj = (float)(j0 + sub * 4);
            float d, e0, e1, e2, e3;
            d = p.x - (bi + 0.f); exv.x = __expf(-d * d * INVC_CELL);
            d = p.x - (bi + 1.f); exv.y = __expf(-d * d * INVC_CELL);
            d = p.x - (bi + 2.f); exv.z = __expf(-d * d * INVC_CELL);
            d = p.x - (bi + 3.f); exv.w = __expf(-d * d * INVC_CELL);
            d = p.y - (bj + 0.f); e0 = __expf(-d * d * INVC_CELL);
            d = p.y - (bj + 1.f); e1 = __expf(-d * d * INVC_CELL);
            d = p.y - (bj + 2.f); e2 = __expf(-d * d * INVC_CELL);
            d = p.y - (bj + 3.f); e3 = __expf(-d * d * INVC_CELL);
            ey01 = make_float4(e0, e0, e1, e1);
            ey23 = make_float4(e2, e2, e3, e3);
        }
        __syncwarp();                        // readers of prev chunk done
        *(float4*)&sex [w][pl][sub * 4]     = exv;
        *(float4*)&seyd[w][pl][sub * 8]     = ey01;
        *(float4*)&seyd[w][pl][sub * 8 + 4] = ey23;
        __syncwarp();

        #pragma unroll
        for (int p = 0; p < 8; p++) {
            unsigned long long e0 =
                *(const unsigned long long*)&seyd[w][p][(ty2 * 2) * 2];
            unsigned long long e1 =
                *(const unsigned long long*)&seyd[w][p][(ty2 * 2 + 1) * 2];
            ulonglong2 ex2 = *(const ulonglong2*)&sex[w][p][tx * 4];
            FMA_F32X2(a00,  ex2.x, e0);
            FMA_F32X2(a01v, ex2.y, e0);
            FMA_F32X2(a10,  ex2.x, e1);
            FMA_F32X2(a11,  ex2.y, e1);
        }
    }

    // ---- 4. fixed-order 4-warp combine + write ----------------------------
    sacc[w][lane][0] = a00;  sacc[w][lane][1] = a01v;
    sacc[w][lane][2] = a10;  sacc[w][lane][3] = a11;
    __syncthreads();
    {
        const int l = tid & 31, s = tid >> 5;   // lane l, slot s
        unsigned long long v = sacc[0][l][s], tt;
        ADD_F32X2(tt, v, sacc[1][l][s]); v = tt;
        ADD_F32X2(tt, v, sacc[2][l][s]); v = tt;
        ADD_F32X2(tt, v, sacc[3][l][s]); v = tt;
        int ltx = l & 3, lty2 = l >> 2;
        int jj = s >> 1, ip = s & 1;
        int i = i0 + ltx * 4 + ip * 2;
        int j = j0 + lty2 * 2 + jj;
        *(unsigned long long*)&out[j * RES + i] = v;
    }
}

// ---------------------------------------------------------------------------
extern "C" void kernel_launch(void* const* d_in, const int* in_sizes, int n_in,
                              void* d_out, int out_size) {
    const float* curves = (const float*)d_in[0];
    float* out = (float*)d_out;
    dim3 grid(NT, NT);
    k_fused<<<grid, 128>>>(curves, out);
}